// round 15
// baseline (speedup 1.0000x reference)
#include <cuda_runtime.h>
#include <cuda_bf16.h>
#include <math.h>
#include <stdint.h>

#define Mn  8192
#define En  512
#define INn 384
#define TKn 6
#define NTILE (Mn / 128)
#define NSEED 16

typedef __nv_bfloat16 bf16;

// ------------------------- scratch (__device__ globals; no allocation) -----
__device__ float g_H  [Mn * En];
__device__ float g_EH [Mn * En];
__device__ float g_ET [Mn * En];
__device__ bf16  g_S  [(size_t)Mn * Mn];
__device__ bf16  g_AH[Mn * En];
__device__ bf16  g_BH[Mn * En];
__device__ bf16  g_XH[Mn * INn];
__device__ bf16  g_XL[Mn * INn];
__device__ bf16  g_HH[Mn * En];
__device__ bf16  g_HL[Mn * En];
__device__ bf16  g_UH[Mn * En];
__device__ bf16  g_UL[Mn * En];
__device__ bf16  g_VH[Mn * En];
__device__ bf16  g_VL[Mn * En];
__device__ bf16  g_MH[Mn * En];
__device__ bf16  g_ML[Mn * En];
__device__ bf16  g_Wfc1H[En * INn],      g_Wfc1L[En * INn];
__device__ bf16  g_WhtH[2 * En * En],    g_WhtL[2 * En * En];
__device__ bf16  g_Wl1H[En * En],        g_Wl1L[En * En];
__device__ bf16  g_Wl2H[En * En],        g_Wl2L[En * En];
__device__ bf16  g_Wa1H[(En / 2) * En],  g_Wa1L[(En / 2) * En];
__device__ float g_PMV[Mn * NTILE];
__device__ int   g_PMI[Mn * NTILE];
__device__ float g_NA [Mn * 2];
__device__ float g_NB [Mn * 2];
__device__ float g_EMB[Mn * En];
__device__ float g_G1 [Mn * (En / 2)];
__device__ float g_GV [Mn];
__device__ float g_ATT[Mn];
__device__ float g_PART[256 * En];
__device__ float g_CM [En];
__device__ float g_POOL[En];

// ===================== helpers ==============================================
__device__ __forceinline__ uint32_t smem_u32(const void* p) {
    uint32_t a;
    asm("{ .reg .u64 t; cvta.to.shared.u64 t, %1; cvt.u32.u64 %0, t; }"
        : "=r"(a) : "l"(p));
    return a;
}
__device__ __forceinline__ void cp_async16(uint32_t dst, const void* src) {
    asm volatile("cp.async.cg.shared.global [%0], [%1], 16;"
                 :: "r"(dst), "l"(src) : "memory");
}
__device__ __forceinline__ void cp_commit() {
    asm volatile("cp.async.commit_group;" ::: "memory");
}
__device__ __forceinline__ void cp_wait1() {
    asm volatile("cp.async.wait_group 1;" ::: "memory");
}
__device__ __forceinline__ void cp_wait0() {
    asm volatile("cp.async.wait_group 0;" ::: "memory");
}
__device__ __forceinline__ void stcs32(void* p, uint32_t v) {
    asm volatile("st.global.cs.u32 [%0], %1;" :: "l"(p), "r"(v) : "memory");
}
__device__ __forceinline__ uint16_t ldcs16(const void* p) {
    uint16_t v;
    asm volatile("ld.global.cs.u16 %0, [%1];" : "=h"(v) : "l"(p) : "memory");
    return v;
}
__device__ __forceinline__ void ldm_x4(uint32_t& r0, uint32_t& r1,
                                       uint32_t& r2, uint32_t& r3, uint32_t a) {
    asm volatile("ldmatrix.sync.aligned.m8n8.x4.shared.b16 {%0,%1,%2,%3}, [%4];"
                 : "=r"(r0), "=r"(r1), "=r"(r2), "=r"(r3) : "r"(a));
}
__device__ __forceinline__ void mma16816(float* d, const uint32_t* a, const uint32_t* b) {
    asm volatile(
        "mma.sync.aligned.m16n8k16.row.col.f32.bf16.bf16.f32 "
        "{%0,%1,%2,%3}, {%4,%5,%6,%7}, {%8,%9}, {%0,%1,%2,%3};"
        : "+f"(d[0]), "+f"(d[1]), "+f"(d[2]), "+f"(d[3])
        : "r"(a[0]), "r"(a[1]), "r"(a[2]), "r"(a[3]), "r"(b[0]), "r"(b[1]));
}
__device__ __forceinline__ uint32_t sw128(uint32_t o) { return o ^ ((o >> 3) & 0x70); }
__device__ __forceinline__ bool better(float v2, int i2, float v1, int i1) {
    return (v2 > v1) || (v2 == v1 && i2 < i1);
}
__device__ __forceinline__ float errb(float nalo, float nahi, float nblo, float nbhi) {
    return 1.1f * (nalo * (nbhi + nblo) + nahi * nblo) + 1e-4f * nahi * nbhi;
}

// ===================== mega-split ============================================
struct SplitSeg { const float* src; bf16* hi; bf16* lo; int n4; };
struct SplitArgs { SplitSeg seg[7]; };

__global__ void megasplit_kernel(SplitArgs args)
{
    int i = blockIdx.x * blockDim.x + threadIdx.x;
#pragma unroll
    for (int s = 0; s < 7; s++) {
        const int n4 = args.seg[s].n4;
        if (i < n4) {
            const float4 a = *(const float4*)(args.seg[s].src + i * 4);
            const float v[4] = { a.x, a.y, a.z, a.w };
            bf16 h[4], l[4];
#pragma unroll
            for (int k = 0; k < 4; k++) {
                h[k] = __float2bfloat16(v[k]);
                l[k] = __float2bfloat16(v[k] - __bfloat162float(h[k]));
            }
            bf16* hi = args.seg[s].hi;
            bf16* lo = args.seg[s].lo;
            *(__nv_bfloat162*)(hi + i * 4)     = __nv_bfloat162(h[0], h[1]);
            *(__nv_bfloat162*)(hi + i * 4 + 2) = __nv_bfloat162(h[2], h[3]);
            *(__nv_bfloat162*)(lo + i * 4)     = __nv_bfloat162(l[0], l[1]);
            *(__nv_bfloat162*)(lo + i * 4 + 2) = __nv_bfloat162(l[2], l[3]);
            return;
        }
        i -= n4;
    }
}

// ===================== generic HMMA split GEMM (3-term) ======================
#define STG_BYTES 65536
#define OFF_AH    0
#define OFF_AL    16384
#define OFF_BHg   32768
#define OFF_BLg   49152

template<int ACT, bool ADD_C, int WSPLIT, bool DUAL>
__global__ __launch_bounds__(256)
void hgemm_nt(const bf16* __restrict__ Ah, const bf16* __restrict__ Al,
              const bf16* __restrict__ Bh, const bf16* __restrict__ Bl,
              const float* __restrict__ bias, float* __restrict__ C,
              bf16* __restrict__ Sh, bf16* __restrict__ Sl,
              const float* __restrict__ bias2, float* __restrict__ C2,
              bf16* __restrict__ S2h,
              float salpha, int N, int K)
{
    extern __shared__ char smem[];
    const uint32_t sb = smem_u32(smem);
    const int tid = threadIdx.x;
    const int w = tid >> 5, l = tid & 31;
    const int m0 = (w & 1) * 64;
    const int n0 = (w >> 1) * 32;
    const int arow0 = blockIdx.y * 128;
    const int brow0 = blockIdx.x * 128;

    const int g  = l >> 3, lr = l & 7;
    const int ar  = (g & 1) * 8 + lr;
    const int acb = (g >> 1) * 16;
    const int br  = (g >> 1) * 8 + lr;
    const int bcb = (g & 1) * 16;

    float acc[4][4][4];
#pragma unroll
    for (int i = 0; i < 4; i++)
#pragma unroll
        for (int j = 0; j < 4; j++)
#pragma unroll
            for (int q = 0; q < 4; q++) acc[i][j][q] = 0.0f;

    auto load_stage = [&](int kc, int s) {
        const uint32_t base = sb + s * STG_BYTES;
        const int kof = kc * 64;
#pragma unroll
        for (int i = 0; i < 4; i++) {
            const int v = tid + i * 256;
            const int r = v >> 3;
            const int cb = (v & 7) * 16;
            const uint32_t sw = sw128((uint32_t)(r * 128 + cb));
            const size_t ga = (size_t)(arow0 + r) * K + kof + (v & 7) * 8;
            const size_t gb = (size_t)(brow0 + r) * K + kof + (v & 7) * 8;
            cp_async16(base + OFF_AH + sw, Ah + ga);
            cp_async16(base + OFF_AL + sw, Al + ga);
            cp_async16(base + OFF_BHg + sw, Bh + gb);
            cp_async16(base + OFF_BLg + sw, Bl + gb);
        }
        cp_commit();
    };

    const int NKC = K >> 6;
    load_stage(0, 0);

    for (int kc = 0; kc < NKC; kc++) {
        if (kc + 1 < NKC) { load_stage(kc + 1, (kc + 1) & 1); cp_wait1(); }
        else              { cp_wait0(); }
        __syncthreads();

        const uint32_t base = sb + (kc & 1) * STG_BYTES;
#pragma unroll
        for (int ks = 0; ks < 4; ks++) {
            const int kb = ks * 32;
            uint32_t fah[4][4], fal[4][4];
#pragma unroll
            for (int mf = 0; mf < 4; mf++) {
                const uint32_t ro = (uint32_t)((m0 + mf * 16 + ar) * 128 + kb + acb);
                ldm_x4(fah[mf][0], fah[mf][1], fah[mf][2], fah[mf][3],
                       base + OFF_AH + sw128(ro));
                ldm_x4(fal[mf][0], fal[mf][1], fal[mf][2], fal[mf][3],
                       base + OFF_AL + sw128(ro));
            }
            uint32_t fbh[4][2], fbl[4][2];
#pragma unroll
            for (int np = 0; np < 2; np++) {
                const uint32_t ro = (uint32_t)((n0 + np * 16 + br) * 128 + kb + bcb);
                uint32_t r0, r1, r2, r3;
                ldm_x4(r0, r1, r2, r3, base + OFF_BHg + sw128(ro));
                fbh[np * 2 + 0][0] = r0; fbh[np * 2 + 0][1] = r1;
                fbh[np * 2 + 1][0] = r2; fbh[np * 2 + 1][1] = r3;
                ldm_x4(r0, r1, r2, r3, base + OFF_BLg + sw128(ro));
                fbl[np * 2 + 0][0] = r0; fbl[np * 2 + 0][1] = r1;
                fbl[np * 2 + 1][0] = r2; fbl[np * 2 + 1][1] = r3;
            }
#pragma unroll
            for (int mf = 0; mf < 4; mf++)
#pragma unroll
                for (int nf = 0; nf < 4; nf++) {
                    mma16816(acc[mf][nf], fah[mf], fbh[nf]);
                    mma16816(acc[mf][nf], fah[mf], fbl[nf]);
                    mma16816(acc[mf][nf], fal[mf], fbh[nf]);
                }
        }
        __syncthreads();
    }

    const int qr = l >> 2, qc = (l & 3) * 2;
#pragma unroll
    for (int mf = 0; mf < 4; mf++) {
#pragma unroll
        for (int nf = 0; nf < 4; nf++) {
            const int colg = brow0 + n0 + nf * 8 + qc;
            const bool first = !DUAL || (colg < En);
            const int col = first ? colg : colg - En;
            const float* bp = first ? bias : bias2;
            const float b0 = bp ? bp[col] : 0.0f;
            const float b1 = bp ? bp[col + 1] : 0.0f;
#pragma unroll
            for (int half = 0; half < 2; half++) {
                const int row = arow0 + m0 + mf * 16 + qr + half * 8;
                float v0 = acc[mf][nf][half * 2 + 0] + b0;
                float v1 = acc[mf][nf][half * 2 + 1] + b1;
                if (ACT == 1) {
                    v0 = v0 > 0.0f ? v0 : 0.01f * v0;
                    v1 = v1 > 0.0f ? v1 : 0.01f * v1;
                }
                const size_t o = (size_t)row * (DUAL ? En : N) + col;
                float* Cp = first ? C : C2;
                if (ADD_C) {
                    float2 old = *(float2*)(Cp + o);
                    v0 += old.x; v1 += old.y;
                }
                *(float2*)(Cp + o) = make_float2(v0, v1);
                if (DUAL) {
                    const float a = first ? salpha : 1.0f;
                    bf16* Sp = first ? Sh : S2h;
                    const float s0 = v0 * a, s1 = v1 * a;
                    *(__nv_bfloat162*)(Sp + o) =
                        __nv_bfloat162(__float2bfloat16(s0), __float2bfloat16(s1));
                } else if (WSPLIT >= 1) {
                    const float s0 = v0 * salpha, s1 = v1 * salpha;
                    const bf16 h0 = __float2bfloat16(s0);
                    const bf16 h1 = __float2bfloat16(s1);
                    Sh[o]     = h0;
                    Sh[o + 1] = h1;
                    if (WSPLIT == 2) {
                        Sl[o]     = __float2bfloat16(s0 - __bfloat162float(h0));
                        Sl[o + 1] = __float2bfloat16(s1 - __bfloat162float(h1));
                    }
                }
            }
        }
    }
}

// ===================== 1-term HMMA attn GEMM + per-tile ub max ===============
#define ATN_STG  32768
#define ATN_BH   16384

__global__ __launch_bounds__(256)
void attn_hmma_kernel(const bf16* __restrict__ Ah, const bf16* __restrict__ Bh,
                      const float* __restrict__ nA, const float* __restrict__ nB,
                      bf16* __restrict__ S,
                      float* __restrict__ PMV, int* __restrict__ PMI)
{
    extern __shared__ char smem[];
    const uint32_t sb = smem_u32(smem);
    const int tid = threadIdx.x;
    const int w = tid >> 5, l = tid & 31;
    const int m0 = (w & 1) * 64;
    const int n0 = (w >> 1) * 32;
    const int arow0 = blockIdx.y * 128;
    const int brow0 = blockIdx.x * 128;

    const int g  = l >> 3, lr = l & 7;
    const int ar  = (g & 1) * 8 + lr;
    const int acb = (g >> 1) * 16;
    const int br  = (g >> 1) * 8 + lr;
    const int bcb = (g & 1) * 16;

    float acc[4][4][4];
#pragma unroll
    for (int i = 0; i < 4; i++)
#pragma unroll
        for (int j = 0; j < 4; j++)
#pragma unroll
            for (int q = 0; q < 4; q++) acc[i][j][q] = 0.0f;

    auto load_stage = [&](int kc, int s) {
        const uint32_t base = sb + s * ATN_STG;
        const int kof = kc * 64;
#pragma unroll
        for (int i = 0; i < 4; i++) {
            const int v = tid + i * 256;
            const int r = v >> 3;
            const int cb = (v & 7) * 16;
            const uint32_t sw = sw128((uint32_t)(r * 128 + cb));
            const size_t ga = (size_t)(arow0 + r) * En + kof + (v & 7) * 8;
            const size_t gb = (size_t)(brow0 + r) * En + kof + (v & 7) * 8;
            cp_async16(base + sw, Ah + ga);
            cp_async16(base + ATN_BH + sw, Bh + gb);
        }
        cp_commit();
    };

    load_stage(0, 0);
    const int NKC = En / 64;
    for (int kc = 0; kc < NKC; kc++) {
        if (kc + 1 < NKC) { load_stage(kc + 1, (kc + 1) & 1); cp_wait1(); }
        else              { cp_wait0(); }
        __syncthreads();

        const uint32_t base = sb + (kc & 1) * ATN_STG;
#pragma unroll
        for (int ks = 0; ks < 4; ks++) {
            const int kb = ks * 32;
            uint32_t fah[4][4];
#pragma unroll
            for (int mf = 0; mf < 4; mf++) {
                const uint32_t ro = (uint32_t)((m0 + mf * 16 + ar) * 128 + kb + acb);
                ldm_x4(fah[mf][0], fah[mf][1], fah[mf][2], fah[mf][3],
                       base + sw128(ro));
            }
            uint32_t fbh[4][2];
#pragma unroll
            for (int np = 0; np < 2; np++) {
                const uint32_t ro = (uint32_t)((n0 + np * 16 + br) * 128 + kb + bcb);
                uint32_t r0, r1, r2, r3;
                ldm_x4(r0, r1, r2, r3, base + ATN_BH + sw128(ro));
                fbh[np * 2 + 0][0] = r0; fbh[np * 2 + 0][1] = r1;
                fbh[np * 2 + 1][0] = r2; fbh[np * 2 + 1][1] = r3;
            }
#pragma unroll
            for (int mf = 0; mf < 4; mf++)
#pragma unroll
                for (int nf = 0; nf < 4; nf++)
                    mma16816(acc[mf][nf], fah[mf], fbh[nf]);
        }
        __syncthreads();
    }

    const int qr = l >> 2, qc = (l & 3) * 2;
#pragma unroll
    for (int mf = 0; mf < 4; mf++) {
        const int row = arow0 + m0 + mf * 16 + qr;
#pragma unroll
        for (int nf = 0; nf < 4; nf++) {
            const int col = brow0 + n0 + nf * 8 + qc;
            __nv_bfloat162 p0(__float2bfloat16(acc[mf][nf][0]),
                              __float2bfloat16(acc[mf][nf][1]));
            __nv_bfloat162 p1(__float2bfloat16(acc[mf][nf][2]),
                              __float2bfloat16(acc[mf][nf][3]));
            stcs32(S + (size_t)row * Mn + col, *(uint32_t*)&p0);
            stcs32(S + (size_t)(row + 8) * Mn + col, *(uint32_t*)&p1);
        }
    }

    float nblo[8], nbhi[8];
#pragma unroll
    for (int nf = 0; nf < 4; nf++) {
#pragma unroll
        for (int q = 0; q < 2; q++) {
            const int j = brow0 + n0 + nf * 8 + qc + q;
            nblo[nf * 2 + q] = nB[j * 2 + 0];
            nbhi[nf * 2 + q] = nB[j * 2 + 1];
        }
    }

    float* smx = (float*)smem;
    int*   smi = (int*)(smem + 2048);
#pragma unroll
    for (int mf = 0; mf < 4; mf++) {
#pragma unroll
        for (int half = 0; half < 2; half++) {
            const int rowg = arow0 + m0 + mf * 16 + qr + half * 8;
            const float nalo = nA[rowg * 2 + 0];
            const float nahi = nA[rowg * 2 + 1];
            const int rowl = m0 + mf * 16 + qr + half * 8;
            float bmx = -INFINITY; int bmi = 0x7fffffff;
#pragma unroll
            for (int nf = 0; nf < 4; nf++) {
#pragma unroll
                for (int q = 0; q < 2; q++) {
                    const float ub = acc[mf][nf][half * 2 + q]
                                   + errb(nalo, nahi, nblo[nf * 2 + q], nbhi[nf * 2 + q]);
                    const int col = n0 + nf * 8 + qc + q;
                    if (better(ub, col, bmx, bmi)) { bmx = ub; bmi = col; }
                }
            }
#pragma unroll
            for (int o = 1; o <= 2; o <<= 1) {
                const float ov = __shfl_xor_sync(0xffffffffu, bmx, o);
                const int   oi = __shfl_xor_sync(0xffffffffu, bmi, o);
                if (better(ov, oi, bmx, bmi)) { bmx = ov; bmi = oi; }
            }
            if ((l & 3) == 0) { smx[rowl * 4 + (w >> 1)] = bmx; smi[rowl * 4 + (w >> 1)] = bmi; }
        }
    }
    __syncthreads();
    if (tid < 128) {
        float bmx = smx[tid * 4]; int bmi = smi[tid * 4];
#pragma unroll
        for (int c = 1; c < 4; c++) {
            const float ov = smx[tid * 4 + c]; const int oi = smi[tid * 4 + c];
            if (better(ov, oi, bmx, bmi)) { bmx = ov; bmi = oi; }
        }
        const size_t o = (size_t)(arow0 + tid) * NTILE + blockIdx.x;
        PMV[o] = bmx;
        PMI[o] = brow0 + bmi;
    }
}

// ---- merged row norms --------------------------------------------------------
__global__ void rownorm2_kernel(const float* __restrict__ EH,
                                const float* __restrict__ ET, float scale,
                                float* __restrict__ nA, float* __restrict__ nB)
{
    const int half = blockIdx.x >= (Mn / 8);
    const int rb = half ? blockIdx.x - Mn / 8 : blockIdx.x;
    const int row = rb * 8 + (threadIdx.x >> 5);
    const int lane = threadIdx.x & 31;
    const float* X = half ? ET : EH;
    const float alpha = half ? 1.0f : scale;
    float* nrm = half ? nB : nA;

    const float4* x4 = (const float4*)(X + (size_t)row * En);
    float slo = 0.0f, shi = 0.0f;
    for (int k = lane; k < En / 4; k += 32) {
        const float4 v = x4[k];
        const float a[4] = { v.x * alpha, v.y * alpha, v.z * alpha, v.w * alpha };
#pragma unroll
        for (int q = 0; q < 4; q++) {
            const float h = __bfloat162float(__float2bfloat16(a[q]));
            const float d = a[q] - h;
            slo += d * d;
            shi += h * h;
        }
    }
#pragma unroll
    for (int o = 16; o > 0; o >>= 1) {
        slo += __shfl_xor_sync(0xffffffffu, slo, o);
        shi += __shfl_xor_sync(0xffffffffu, shi, o);
    }
    if (lane == 0) {
        nrm[row * 2 + 0] = sqrtf(slo);
        nrm[row * 2 + 1] = sqrtf(shi);
    }
}

// ===================== fused certified top-6 + combine (256 threads) =========
__global__ __launch_bounds__(256)
void topk_combine_kernel(const bf16* __restrict__ S,
                         const float* __restrict__ PMV, const int* __restrict__ PMI,
                         const float* __restrict__ EH, const float* __restrict__ ET,
                         const float* __restrict__ nA, const float* __restrict__ nB,
                         float scale,
                         bf16* __restrict__ Uh, bf16* __restrict__ Ul,
                         bf16* __restrict__ Vh, bf16* __restrict__ Vl)
{
    const int row = blockIdx.x;
    const int t = threadIdx.x;              // 0..255
    const int lane = t & 31, wp = t >> 5;   // 8 warps
    const int tilehalf = t >> 7;            // 0: warps 0-3, 1: warps 4-7
    const int tcol = t & 127;

    __shared__ float sh_eh[En];
    __shared__ float sh_nb[TKn][En];
    __shared__ float s_tmv[NTILE];
    __shared__ int   s_tmi[NTILE];
    __shared__ int   seedcol[NSEED];
    __shared__ float seedval[NSEED];
    __shared__ float sh_L;
    __shared__ float swv[8]; __shared__ int swi[8]; __shared__ int swt[8];
    __shared__ int   sh_win;
    __shared__ float w6[TKn]; __shared__ int idx6[TKn];
    __shared__ float p[TKn]; __shared__ float q[TKn];
    __shared__ float wred[8][2 * TKn];

    for (int k = t; k < En / 4; k += 256)
        ((float4*)sh_eh)[k] = ((const float4*)(EH + (size_t)row * En))[k];
    if (t < NTILE) {
        s_tmv[t] = PMV[(size_t)row * NTILE + t];
        s_tmi[t] = PMI[(size_t)row * NTILE + t];
    }
    __syncthreads();

    // ---- seed selection: top-NSEED tiles by ub (warp 0) ----
    if (wp == 0) {
        float v0 = s_tmv[lane], v1 = s_tmv[lane + 32];
        int   i0 = lane, i1 = lane + 32;
        for (int s = 0; s < NSEED; s++) {
            float cv; int ct;
            if (v0 >= v1) { cv = v0; ct = i0; } else { cv = v1; ct = i1; }
#pragma unroll
            for (int o = 16; o > 0; o >>= 1) {
                const float ov = __shfl_xor_sync(0xffffffffu, cv, o);
                const int   ot = __shfl_xor_sync(0xffffffffu, ct, o);
                if (ov > cv || (ov == cv && ot < ct)) { cv = ov; ct = ot; }
            }
            if (lane == 0) seedcol[s] = s_tmi[ct];
            if (i0 == ct) v0 = -INFINITY;
            if (i1 == ct) v1 = -INFINITY;
        }
    }
    __syncthreads();

    // ---- warp-cooperative exact dots of NSEED seed cols (8 warps, 2 rounds) --
    const float4* eh4 = (const float4*)sh_eh;
    for (int r = 0; r < NSEED / 8; r++) {
        const int s = wp + 8 * r;
        const int j = seedcol[s];
        const float4* et4 = (const float4*)(ET + (size_t)j * En);
        float acc = 0.0f;
#pragma unroll
        for (int k = lane; k < En / 4; k += 32) {
            const float4 a = eh4[k];
            const float4 b = et4[k];
            acc += a.x * b.x + a.y * b.y + a.z * b.z + a.w * b.w;
        }
#pragma unroll
        for (int o = 16; o > 0; o >>= 1) acc += __shfl_xor_sync(0xffffffffu, acc, o);
        if (lane == 0) seedval[s] = acc * scale;
    }
    __syncthreads();
    if (t == 0) {
        float top[TKn];
#pragma unroll
        for (int k = 0; k < TKn; k++) top[k] = -INFINITY;
        for (int s = 0; s < NSEED; s++) {
            float v = seedval[s];
            if (v > top[TKn - 1]) {
                top[TKn - 1] = v;
#pragma unroll
                for (int k = TKn - 1; k > 0; k--)
                    if (top[k] > top[k - 1]) { float tv = top[k]; top[k] = top[k - 1]; top[k - 1] = tv; }
            }
        }
        sh_L = top[TKn - 1];
    }
    __syncthreads();
    const float L = sh_L;

    // ---- candidate scan: 2 tiles per iteration (warp-uniform filters) -------
    const float nalo = nA[row * 2 + 0], nahi = nA[row * 2 + 1];
    float lv[TKn]; int li[TKn];
#pragma unroll
    for (int k = 0; k < TKn; k++) { lv[k] = -INFINITY; li[k] = 0x7fffffff; }

    for (int tile = 0; tile < NTILE; tile += 2) {
        const int mytile = tile + tilehalf;
        if (s_tmv[mytile] >= L) {          // uniform within each warp
            const int col = mytile * 128 + tcol;
            const uint16_t raw = ldcs16(S + (size_t)row * Mn + col);
            const float ap = __bfloat162float(*(const bf16*)&raw);
            const float nbh = nB[col * 2 + 1];
            const float b = errb(nalo, nahi, nB[col * 2 + 0], nbh) + 0.005f * nahi * nbh;
            const bool pass = (ap + b >= L);
            unsigned mask = __ballot_sync(0xffffffffu, pass);
            while (mask) {
                const int src = __ffs(mask) - 1;
                mask &= mask - 1;
                const int j = __shfl_sync(0xffffffffu, col, src);
                const float4* et4 = (const float4*)(ET + (size_t)j * En);
                float acc = 0.0f;
#pragma unroll
                for (int k = lane; k < En / 4; k += 32) {
                    const float4 a = eh4[k];
                    const float4 bb = et4[k];
                    acc += a.x * bb.x + a.y * bb.y + a.z * bb.z + a.w * bb.w;
                }
#pragma unroll
                for (int o = 16; o > 0; o >>= 1) acc += __shfl_xor_sync(0xffffffffu, acc, o);
                if (lane == src) {
                    const float s = acc * scale;
                    if (better(s, j, lv[TKn - 1], li[TKn - 1])) {
                        lv[TKn - 1] = s; li[TKn - 1] = j;
#pragma unroll
                        for (int k = TKn - 1; k > 0; k--) {
                            if (better(lv[k], li[k], lv[k - 1], li[k - 1])) {
                                float tv = lv[k]; lv[k] = lv[k - 1]; lv[k - 1] = tv;
                                int   ti = li[k]; li[k] = li[k - 1]; li[k - 1] = ti;
                            }
                        }
                    }
                }
            }
        }
    }

    // ---- final exact top-6 tournament over 256 per-thread lists -------------
    __shared__ float sv[256 * TKn];
    __shared__ int   si[256 * TKn];
    __shared__ int   sp[256];
#pragma unroll
    for (int k = 0; k < TKn; k++) { sv[t * TKn + k] = lv[k]; si[t * TKn + k] = li[k]; }
    sp[t] = 0;
    __syncthreads();
    for (int sel = 0; sel < TKn; sel++) {
        const int pp = sp[t];
        float cv = sv[t * TKn + pp];
        int   ci = si[t * TKn + pp];
        int   tt = t;
#pragma unroll
        for (int o = 16; o > 0; o >>= 1) {
            const float ov = __shfl_xor_sync(0xffffffffu, cv, o);
            const int   oi = __shfl_xor_sync(0xffffffffu, ci, o);
            const int   ot = __shfl_xor_sync(0xffffffffu, tt, o);
            if (better(ov, oi, cv, ci)) { cv = ov; ci = oi; tt = ot; }
        }
        if (lane == 0) { swv[wp] = cv; swi[wp] = ci; swt[wp] = tt; }
        __syncthreads();
        if (t == 0) {
            int wi = 0;
#pragma unroll
            for (int c = 1; c < 8; c++)
                if (better(swv[c], swi[c], swv[wi], swi[wi])) wi = c;
            w6[sel] = swv[wi];
            idx6[sel] = swi[wi];
            sh_win = swt[wi];
        }
        __syncthreads();
        if (t == sh_win && sp[t] < TKn - 1) sp[t]++;
        __syncthreads();
    }

    // =================== fused combine phase ===================
#pragma unroll
    for (int k = 0; k < TKn; k++) {
        const float4* src = (const float4*)(ET + (size_t)idx6[k] * En);
        for (int e = t; e < En / 4; e += 256) ((float4*)sh_nb[k])[e] = src[e];
    }
    if (t == 0) {
        float mx = w6[0];
        for (int k = 1; k < TKn; k++) mx = fmaxf(mx, w6[k]);
        float s = 0.0f;
        for (int k = 0; k < TKn; k++) { p[k] = expf(w6[k] - mx); s += p[k]; }
        float inv = 1.0f / s;
        for (int k = 0; k < TKn; k++) p[k] *= inv;
    }
    __syncthreads();

    float pn[TKn], pg[TKn];
#pragma unroll
    for (int k = 0; k < TKn; k++) { pn[k] = 0.0f; pg[k] = 0.0f; }
    for (int e = t; e < En; e += 256) {
        const float eh = sh_eh[e];
#pragma unroll
        for (int k = 0; k < TKn; k++) {
            const float nb = sh_nb[k][e];
            pn[k] += nb;
            pg[k] += tanhf((2.0f - p[k]) * eh + p[k] * nb);
        }
    }
#pragma unroll
    for (int k = 0; k < TKn; k++) {
#pragma unroll
        for (int o = 16; o > 0; o >>= 1) {
            pn[k] += __shfl_xor_sync(0xffffffffu, pn[k], o);
            pg[k] += __shfl_xor_sync(0xffffffffu, pg[k], o);
        }
    }
    if (lane == 0) {
#pragma unroll
        for (int k = 0; k < TKn; k++) {
            wred[wp][k] = pn[k];
            wred[wp][TKn + k] = pg[k];
        }
    }
    __syncthreads();
    if (t == 0) {
        float ka[TKn];
        float mx = -INFINITY;
#pragma unroll
        for (int k = 0; k < TKn; k++) {
            float sn = 0.0f, sg = 0.0f;
#pragma unroll
            for (int c = 0; c < 8; c++) { sn += wred[c][k]; sg += wred[c][TKn + k]; }
            ka[k] = sn * sg;
            mx = fmaxf(mx, ka[k]);
        }
        float s = 0.0f;
        for (int k = 0; k < TKn; k++) { q[k] = expf(ka[k] - mx); s += q[k]; }
        float inv = 1.0f / s;
        for (int k = 0; k < TKn; k++) q[k] *= inv;
    }
    __syncthreads();

    for (int e = t; e < En; e += 256) {
        float en = 0.0f;
#pragma unroll
        for (int k = 0; k < TKn; k++) en = fmaf(q[k], sh_nb[k][e], en);
        const float eh = sh_eh[e];
        const size_t o = (size_t)row * En + e;
        const float u = eh + en, v = eh * en;
        const bf16 uh = __float2bfloat16(u);
        const bf16 vh = __float2bfloat16(v);
        Uh[o] = uh; Ul[o] = __float2bfloat16(u - __bfloat162float(uh));
        Vh[o] = vh; Vl[o] = __float2bfloat16(v - __bfloat162float(vh));
    }
}

// ---- column partial reduce (optionally row-weighted) -----------------------
template<bool W>
__global__ void colred_kernel(const float* __restrict__ X,
                              const float* __restrict__ wgt,
                              float* __restrict__ part, int rows, int cols)
{
    const int col   = blockIdx.x * blockDim.x + threadIdx.x;
    const int chunk = blockIdx.y;
    const int rpc   = rows / gridDim.y;
    const int r0    = chunk * rpc;
    float s = 0.0f;
    for (int r = r0; r < r0 + rpc; r++) {
        float v = X[(size_t)r * cols + col];
        if (W) v *= wgt[r];
        s += v;
    }
    part[chunk * cols + col] = s;
}

// ---- parallel chunk-sum -------------------------------------------------------
__global__ void chunksum_kernel(const float* __restrict__ part,
                                float* __restrict__ outv, float mul)
{
    const int col = blockIdx.x * 8 + (threadIdx.x >> 5);
    const int lane = threadIdx.x & 31;
    float s = 0.0f;
#pragma unroll
    for (int c = lane; c < 256; c += 32) s += part[c * En + col];
#pragma unroll
    for (int o = 16; o > 0; o >>= 1) s += __shfl_xor_sync(0xffffffffu, s, o);
    if (lane == 0) outv[col] = s * mul;
}

__global__ void meanscale_split_kernel(const float* __restrict__ H,
                                       const float* __restrict__ cm,
                                       bf16* __restrict__ hh, bf16* __restrict__ hl)
{
    const int i4 = (blockIdx.x * blockDim.x + threadIdx.x) * 4;
    const int e = i4 & (En - 1);
    const float4 hv = *(const float4*)(H + i4);
    const float4 cv = *(const float4*)(cm + e);
    float v[4] = { (hv.x + cv.x) * 0.5f, (hv.y + cv.y) * 0.5f,
                   (hv.z + cv.z) * 0.5f, (hv.w + cv.w) * 0.5f };
    bf16 hi[4], lo[4];
#pragma unroll
    for (int k = 0; k < 4; k++) {
        hi[k] = __float2bfloat16(v[k]);
        lo[k] = __float2bfloat16(v[k] - __bfloat162float(hi[k]));
    }
    *(__nv_bfloat162*)(hh + i4)     = __nv_bfloat162(hi[0], hi[1]);
    *(__nv_bfloat162*)(hh + i4 + 2) = __nv_bfloat162(hi[2], hi[3]);
    *(__nv_bfloat162*)(hl + i4)     = __nv_bfloat162(lo[0], lo[1]);
    *(__nv_bfloat162*)(hl + i4 + 2) = __nv_bfloat162(lo[2], lo[3]);
}

// ---- g = G1 @ a2_w^T + a2_b -------------------------------------------------
__global__ void matvec_kernel(const float* __restrict__ G1,
                              const float* __restrict__ a2w,
                              const float* __restrict__ a2b,
                              float* __restrict__ gv)
{
    const int warp = (blockIdx.x * blockDim.x + threadIdx.x) >> 5;
    const int lane = threadIdx.x & 31;
    if (warp >= Mn) return;
    const float* rowp = G1 + (size_t)warp * (En / 2);
    float s = 0.0f;
    for (int j = lane; j < En / 2; j += 32) s = fmaf(rowp[j], a2w[j], s);
#pragma unroll
    for (int o = 16; o > 0; o >>= 1) s += __shfl_xor_sync(0xffffffffu, s, o);
    if (lane == 0) gv[warp] = s + a2b[0];
}

__global__ void softmax_att_kernel(const float* __restrict__ gv, float* __restrict__ att)
{
    __shared__ float red[1024];
    const int tid = threadIdx.x;
    float mx = -INFINITY;
    for (int i = tid; i < Mn; i += 1024) mx = fmaxf(mx, gv[i]);
    red[tid] = mx; __syncthreads();
    for (int s = 512; s > 0; s >>= 1) { if (tid < s) red[tid] = fmaxf(red[tid], red[tid + s]); __syncthreads(); }
    mx = red[0]; __syncthreads();
    float se = 0.0f;
    for (int i = tid; i < Mn; i += 1024) se += expf(gv[i] - mx);
    red[tid] = se; __syncthreads();
    for (int s = 512; s > 0; s >>= 1) { if (tid < s) red[tid] += red[tid + s]; __syncthreads(); }
    const float inv = 1.0f / red[0];
    for (int i = tid; i < Mn; i += 1024) att[i] = expf(gv[i] - mx) * inv;
}

__global__ void ln_kernel(const float* __restrict__ pooled,
                          const float* __restrict__ g,
                          const float* __restrict__ b,
                          float* __restrict__ out)
{
    __shared__ float red[En];
    const int e = threadIdx.x;
    const float s = pooled[e];
    red[e] = s; __syncthreads();
    for (int st = 256; st > 0; st >>= 1) { if (e < st) red[e] += red[e + st]; __syncthreads(); }
    const float mu = red[0] * (1.0f / (float)En);
    __syncthreads();
    const float d = s - mu;
    red[e] = d * d; __syncthreads();
    for (int st = 256; st > 0; st >>= 1) { if (e < st) red[e] += red[e + st]; __syncthreads(); }
    const float var = red[0] * (1.0f / (float)En);
    out[e] = d * rsqrtf(var + 1e-5f) * g[e] + b[e];
}

// --------------------------------------------------------------------------
extern "C" void kernel_launch(void* const* d_in, const int* in_sizes, int n_in,
                              void* d_out, int out_size)
{
    (void)in_sizes; (void)n_in; (void)out_size;
    const float* x    = (const float*)d_in[0];
    const float* fc1w = (const float*)d_in[1];
    const float* fc1b = (const float*)d_in[2];
    const float* whw  = (const float*)d_in[3];
    const float* whb  = (const float*)d_in[4];
    const float* wtw  = (const float*)d_in[5];
    const float* wtb  = (const float*)d_in[6];
    const float* l1w  = (const float*)d_in[7];
    const float* l1b  = (const float*)d_in[8];
    const float* l2w  = (const float*)d_in[9];
    const float* l2b  = (const float*)d_in[10];
    const float* a1w  = (const float*)d_in[11];
    const float* a1b  = (const float*)d_in[12];
    const float* a2w  = (const float*)d_in[13];
    const float* a2b  = (const float*)d_in[14];
    const float* lng  = (const float*)d_in[15];
    const float* lnb  = (const float*)d_in[16];
    float* out = (float*)d_out;

    float *H, *EH, *ET, *PMV, *NA, *NB, *EMB, *G1, *GV, *ATT, *PART, *CM, *POOL;
    bf16 *S, *AH, *BH, *XH, *XL, *HH, *HL, *UH, *UL, *VH, *VL, *MH, *ML;
    bf16 *Wfc1H, *Wfc1L, *WhtH, *WhtL, *Wl1H, *Wl1L, *Wl2H, *Wl2L, *Wa1H, *Wa1L;
    int *PMI;
    cudaGetSymbolAddress((void**)&H,    g_H);
    cudaGetSymbolAddress((void**)&EH,   g_EH);
    cudaGetSymbolAddress((void**)&ET,   g_ET);
    cudaGetSymbolAddress((void**)&S,    g_S);
    cudaGetSymbolAddress((void**)&PMV,  g_PMV);
    cudaGetSymbolAddress((void**)&PMI,  g_PMI);
    cudaGetSymbolAddress((void**)&NA,   g_NA);
    cudaGetSymbolAddress((void**)&NB,   g_NB);
    cudaGetSymbolAddress((void**)&AH,   g_AH);
    cudaGetSymbolAddress((void**)&BH,   g_BH);
    cudaGetSymbolAddress((void**)&XH,   g_XH);
    cudaGetSymbolAddress((void**)&XL,   g_XL);
    cudaGetSymbolAddress((void**)&HH,   g_HH);
    cudaGetSymbolAddress((void**)&HL,   g_HL);
    cudaGetSymbolAddress((void**)&UH,   g_UH);
    cudaGetSymbolAddress((void**)&UL,   g_UL);
    cudaGetSymbolAddress((void**)&VH,   g_VH);
    cudaGetSymbolAddress((void**)&VL,   g_VL);
    cudaGetSymbolAddress((void**)&MH,   g_MH);
    cudaGetSymbolAddress((void**)&ML,   g_ML);
    cudaGetSymbolAddress((void**)&Wfc1H, g_Wfc1H);
    cudaGetSymbolAddress((void**)&Wfc1L, g_Wfc1L);
    cudaGetSymbolAddress((void**)&WhtH,  g_WhtH);
    cudaGetSymbolAddress((void**)&WhtL,  g_WhtL);
    cudaGetSymbolAddress((void**)&Wl1H,  g_Wl1H);
    cudaGetSymbolAddress((void**)&Wl1L,  g_Wl1L);
    cudaGetSymbolAddress((void**)&Wl2H,  g_Wl2H);
    cudaGetSymbolAddress((void**)&Wl2L,  g_Wl2L);
    cudaGetSymbolAddress((void**)&Wa1H,  g_Wa1H);
    cudaGetSymbolAddress((void**)&Wa1L,  g_Wa1L);
    cudaGetSymbolAddress((void**)&EMB,  g_EMB);
    cudaGetSymbolAddress((void**)&G1,   g_G1);
    cudaGetSymbolAddress((void**)&GV,   g_GV);
    cudaGetSymbolAddress((void**)&ATT,  g_ATT);
    cudaGetSymbolAddress((void**)&PART, g_PART);
    cudaGetSymbolAddress((void**)&CM,   g_CM);
    cudaGetSymbolAddress((void**)&POOL, g_POOL);

    const float scale = 1.0f / sqrtf((float)En);

    cudaFuncSetAttribute(hgemm_nt<1, false, 0, false>, cudaFuncAttributeMaxDynamicSharedMemorySize, 2 * STG_BYTES);
    cudaFuncSetAttribute(hgemm_nt<0, false, 0, true >, cudaFuncAttributeMaxDynamicSharedMemorySize, 2 * STG_BYTES);
    cudaFuncSetAttribute(hgemm_nt<1, true,  2, false>, cudaFuncAttributeMaxDynamicSharedMemorySize, 2 * STG_BYTES);
    cudaFuncSetAttribute(attn_hmma_kernel, cudaFuncAttributeMaxDynamicSharedMemorySize, 2 * ATN_STG);

    // 0) mega-split: x + all weights (one launch)
    SplitArgs sa;
    sa.seg[0] = { x,    XH,    XL,    Mn * INn / 4 };
    sa.seg[1] = { fc1w, Wfc1H, Wfc1L, En * INn / 4 };
    sa.seg[2] = { whw,  WhtH,  WhtL,  En * En / 4 };
    sa.seg[3] = { wtw,  WhtH + En * En, WhtL + En * En, En * En / 4 };
    sa.seg[4] = { l1w,  Wl1H,  Wl1L,  En * En / 4 };
    sa.seg[5] = { l2w,  Wl2H,  Wl2L,  En * En / 4 };
    sa.seg[6] = { a1w,  Wa1H,  Wa1L,  (En / 2) * En / 4 };
    int totq = 0;
    for (int s = 0; s < 7; s++) totq += sa.seg[s].n4;
    megasplit_kernel<<<(totq + 255) / 256, 256>>>(sa);

    // 1) h = lrelu(x @ fc1^T + b)
    hgemm_nt<1, false, 0, false><<<dim3(En / 128, Mn / 128), 256, 2 * STG_BYTES>>>(
        XH, XL, Wfc1H, Wfc1L, fc1b, H, nullptr, nullptr, nullptr, nullptr, nullptr, 0.0f, En, INn);
    // 2) h = (h + colmean(h)) * 0.5  -> split
    colred_kernel<false><<<dim3(En / 128, 256), 128>>>(H, nullptr, PART, Mn, En);
    chunksum_kernel<<<En / 8, 256>>>(PART, CM, 1.0f / (float)Mn);
    meanscale_split_kernel<<<(Mn * En) / 1024, 256>>>(H, CM, HH, HL);
    // 3) fused e_h + e_t
    hgemm_nt<0, false, 0, true><<<dim3(2 * En / 128, Mn / 128), 256, 2 * STG_BYTES>>>(
        HH, HL, WhtH, WhtL, whb, EH, AH, nullptr, wtb, ET, BH, scale, En, En);
    rownorm2_kernel<<<Mn / 4, 256>>>(EH, ET, scale, NA, NB);
    // 4) S_approx = Ah @ Bh^T (1-term, bf16 .cs) + per-tile row ub maxima
    attn_hmma_kernel<<<dim3(NTILE, NTILE), 256, 2 * ATN_STG>>>(AH, BH, NA, NB, S, PMV, PMI);
    // 5+6) fused certified top-6 + combine (256 threads)
    topk_combine_kernel<<<Mn, 256>>>(S, PMV, PMI, EH, ET, NA, NB, scale, UH, UL, VH, VL);
    // 7) emb = lrelu(U@l1^T+b) + lrelu(V@l2^T+b)
    hgemm_nt<1, false, 0, false><<<dim3(En / 128, Mn / 128), 256, 2 * STG_BYTES>>>(
        UH, UL, Wl1H, Wl1L, l1b, EMB, nullptr, nullptr, nullptr, nullptr, nullptr, 0.0f, En, En);
    hgemm_nt<1, true, 2, false><<<dim3(En / 128, Mn / 128), 256, 2 * STG_BYTES>>>(
        VH, VL, Wl2H, Wl2L, l2b, EMB, MH, ML, nullptr, nullptr, nullptr, 1.0f, En, En);
    // 8) readout gate
    hgemm_nt<1, false, 0, false><<<dim3((En / 2) / 128, Mn / 128), 256, 2 * STG_BYTES>>>(
        MH, ML, Wa1H, Wa1L, a1b, G1, nullptr, nullptr, nullptr, nullptr, nullptr, 0.0f, En / 2, En);
    matvec_kernel<<<Mn / 8, 256>>>(G1, a2w, a2b, GV);
    // 9) softmax over nodes, weighted pool, layernorm
    softmax_att_kernel<<<1, 1024>>>(GV, ATT);
    colred_kernel<true><<<dim3(En / 128, 256), 128>>>(EMB, ATT, PART, Mn, En);
    chunksum_kernel<<<En / 8, 256>>>(PART, POOL, 1.0f);
    ln_kernel<<<1, En>>>(POOL, lng, lnb, out);
}

// round 16
// speedup vs baseline: 1.1411x; 1.1411x over previous
#include <cuda_runtime.h>
#include <cuda_bf16.h>
#include <math.h>
#include <stdint.h>

#define Mn  8192
#define En  512
#define INn 384
#define TKn 6
#define NTILE (Mn / 128)
#define NSEED 16

typedef __nv_bfloat16 bf16;

// ------------------------- scratch (__device__ globals; no allocation) -----
__device__ float g_H  [Mn * En];
__device__ float g_EH [Mn * En];
__device__ float g_ET [Mn * En];
__device__ bf16  g_S  [(size_t)Mn * Mn];
__device__ bf16  g_AH[Mn * En];
__device__ bf16  g_BH[Mn * En];
__device__ bf16  g_XH[Mn * INn];
__device__ bf16  g_XL[Mn * INn];
__device__ bf16  g_HH[Mn * En];
__device__ bf16  g_HL[Mn * En];
__device__ bf16  g_UH[Mn * En];
__device__ bf16  g_UL[Mn * En];
__device__ bf16  g_VH[Mn * En];
__device__ bf16  g_VL[Mn * En];
__device__ bf16  g_MH[Mn * En];
__device__ bf16  g_ML[Mn * En];
__device__ bf16  g_Wfc1H[En * INn],      g_Wfc1L[En * INn];
__device__ bf16  g_WhtH[2 * En * En],    g_WhtL[2 * En * En];
__device__ bf16  g_Wl1H[En * En],        g_Wl1L[En * En];
__device__ bf16  g_Wl2H[En * En],        g_Wl2L[En * En];
__device__ bf16  g_Wa1H[(En / 2) * En],  g_Wa1L[(En / 2) * En];
__device__ float g_PMV[Mn * NTILE];
__device__ int   g_PMI[Mn * NTILE];
__device__ float g_NA [Mn * 2];
__device__ float g_NB [Mn * 2];
__device__ float g_EMB[Mn * En];
__device__ float g_G1 [Mn * (En / 2)];
__device__ float g_GV [Mn];
__device__ float g_ATT[Mn];
__device__ float g_PART[256 * En];
__device__ float g_CM [En];
__device__ float g_POOL[En];

// ===================== helpers ==============================================
__device__ __forceinline__ uint32_t smem_u32(const void* p) {
    uint32_t a;
    asm("{ .reg .u64 t; cvta.to.shared.u64 t, %1; cvt.u32.u64 %0, t; }"
        : "=r"(a) : "l"(p));
    return a;
}
__device__ __forceinline__ void cp_async16(uint32_t dst, const void* src) {
    asm volatile("cp.async.cg.shared.global [%0], [%1], 16;"
                 :: "r"(dst), "l"(src) : "memory");
}
__device__ __forceinline__ void cp_commit() {
    asm volatile("cp.async.commit_group;" ::: "memory");
}
__device__ __forceinline__ void cp_wait1() {
    asm volatile("cp.async.wait_group 1;" ::: "memory");
}
__device__ __forceinline__ void cp_wait0() {
    asm volatile("cp.async.wait_group 0;" ::: "memory");
}
__device__ __forceinline__ void stcs32(void* p, uint32_t v) {
    asm volatile("st.global.cs.u32 [%0], %1;" :: "l"(p), "r"(v) : "memory");
}
__device__ __forceinline__ uint16_t ldcs16(const void* p) {
    uint16_t v;
    asm volatile("ld.global.cs.u16 %0, [%1];" : "=h"(v) : "l"(p) : "memory");
    return v;
}
__device__ __forceinline__ void ldm_x4(uint32_t& r0, uint32_t& r1,
                                       uint32_t& r2, uint32_t& r3, uint32_t a) {
    asm volatile("ldmatrix.sync.aligned.m8n8.x4.shared.b16 {%0,%1,%2,%3}, [%4];"
                 : "=r"(r0), "=r"(r1), "=r"(r2), "=r"(r3) : "r"(a));
}
__device__ __forceinline__ void mma16816(float* d, const uint32_t* a, const uint32_t* b) {
    asm volatile(
        "mma.sync.aligned.m16n8k16.row.col.f32.bf16.bf16.f32 "
        "{%0,%1,%2,%3}, {%4,%5,%6,%7}, {%8,%9}, {%0,%1,%2,%3};"
        : "+f"(d[0]), "+f"(d[1]), "+f"(d[2]), "+f"(d[3])
        : "r"(a[0]), "r"(a[1]), "r"(a[2]), "r"(a[3]), "r"(b[0]), "r"(b[1]));
}
__device__ __forceinline__ uint32_t sw128(uint32_t o) { return o ^ ((o >> 3) & 0x70); }
__device__ __forceinline__ bool better(float v2, int i2, float v1, int i1) {
    return (v2 > v1) || (v2 == v1 && i2 < i1);
}
__device__ __forceinline__ float errb(float nalo, float nahi, float nblo, float nbhi) {
    return 1.1f * (nalo * (nbhi + nblo) + nahi * nblo) + 1e-4f * nahi * nbhi;
}

// ===================== mega-split ============================================
struct SplitSeg { const float* src; bf16* hi; bf16* lo; int n4; };
struct SplitArgs { SplitSeg seg[7]; };

__global__ void megasplit_kernel(SplitArgs args)
{
    int i = blockIdx.x * blockDim.x + threadIdx.x;
#pragma unroll
    for (int s = 0; s < 7; s++) {
        const int n4 = args.seg[s].n4;
        if (i < n4) {
            const float4 a = *(const float4*)(args.seg[s].src + i * 4);
            const float v[4] = { a.x, a.y, a.z, a.w };
            bf16 h[4], l[4];
#pragma unroll
            for (int k = 0; k < 4; k++) {
                h[k] = __float2bfloat16(v[k]);
                l[k] = __float2bfloat16(v[k] - __bfloat162float(h[k]));
            }
            bf16* hi = args.seg[s].hi;
            bf16* lo = args.seg[s].lo;
            *(__nv_bfloat162*)(hi + i * 4)     = __nv_bfloat162(h[0], h[1]);
            *(__nv_bfloat162*)(hi + i * 4 + 2) = __nv_bfloat162(h[2], h[3]);
            *(__nv_bfloat162*)(lo + i * 4)     = __nv_bfloat162(l[0], l[1]);
            *(__nv_bfloat162*)(lo + i * 4 + 2) = __nv_bfloat162(l[2], l[3]);
            return;
        }
        i -= n4;
    }
}

// ===================== generic HMMA split GEMM (3-term) ======================
#define STG_BYTES 65536
#define OFF_AH    0
#define OFF_AL    16384
#define OFF_BHg   32768
#define OFF_BLg   49152

template<int ACT, bool ADD_C, int WSPLIT, bool DUAL>
__global__ __launch_bounds__(256)
void hgemm_nt(const bf16* __restrict__ Ah, const bf16* __restrict__ Al,
              const bf16* __restrict__ Bh, const bf16* __restrict__ Bl,
              const float* __restrict__ bias, float* __restrict__ C,
              bf16* __restrict__ Sh, bf16* __restrict__ Sl,
              const float* __restrict__ bias2, float* __restrict__ C2,
              bf16* __restrict__ S2h,
              float salpha, int N, int K)
{
    extern __shared__ char smem[];
    const uint32_t sb = smem_u32(smem);
    const int tid = threadIdx.x;
    const int w = tid >> 5, l = tid & 31;
    const int m0 = (w & 1) * 64;
    const int n0 = (w >> 1) * 32;
    const int arow0 = blockIdx.y * 128;
    const int brow0 = blockIdx.x * 128;

    const int g  = l >> 3, lr = l & 7;
    const int ar  = (g & 1) * 8 + lr;
    const int acb = (g >> 1) * 16;
    const int br  = (g >> 1) * 8 + lr;
    const int bcb = (g & 1) * 16;

    float acc[4][4][4];
#pragma unroll
    for (int i = 0; i < 4; i++)
#pragma unroll
        for (int j = 0; j < 4; j++)
#pragma unroll
            for (int q = 0; q < 4; q++) acc[i][j][q] = 0.0f;

    auto load_stage = [&](int kc, int s) {
        const uint32_t base = sb + s * STG_BYTES;
        const int kof = kc * 64;
#pragma unroll
        for (int i = 0; i < 4; i++) {
            const int v = tid + i * 256;
            const int r = v >> 3;
            const int cb = (v & 7) * 16;
            const uint32_t sw = sw128((uint32_t)(r * 128 + cb));
            const size_t ga = (size_t)(arow0 + r) * K + kof + (v & 7) * 8;
            const size_t gb = (size_t)(brow0 + r) * K + kof + (v & 7) * 8;
            cp_async16(base + OFF_AH + sw, Ah + ga);
            cp_async16(base + OFF_AL + sw, Al + ga);
            cp_async16(base + OFF_BHg + sw, Bh + gb);
            cp_async16(base + OFF_BLg + sw, Bl + gb);
        }
        cp_commit();
    };

    const int NKC = K >> 6;
    load_stage(0, 0);

    for (int kc = 0; kc < NKC; kc++) {
        if (kc + 1 < NKC) { load_stage(kc + 1, (kc + 1) & 1); cp_wait1(); }
        else              { cp_wait0(); }
        __syncthreads();

        const uint32_t base = sb + (kc & 1) * STG_BYTES;
#pragma unroll
        for (int ks = 0; ks < 4; ks++) {
            const int kb = ks * 32;
            uint32_t fah[4][4], fal[4][4];
#pragma unroll
            for (int mf = 0; mf < 4; mf++) {
                const uint32_t ro = (uint32_t)((m0 + mf * 16 + ar) * 128 + kb + acb);
                ldm_x4(fah[mf][0], fah[mf][1], fah[mf][2], fah[mf][3],
                       base + OFF_AH + sw128(ro));
                ldm_x4(fal[mf][0], fal[mf][1], fal[mf][2], fal[mf][3],
                       base + OFF_AL + sw128(ro));
            }
            uint32_t fbh[4][2], fbl[4][2];
#pragma unroll
            for (int np = 0; np < 2; np++) {
                const uint32_t ro = (uint32_t)((n0 + np * 16 + br) * 128 + kb + bcb);
                uint32_t r0, r1, r2, r3;
                ldm_x4(r0, r1, r2, r3, base + OFF_BHg + sw128(ro));
                fbh[np * 2 + 0][0] = r0; fbh[np * 2 + 0][1] = r1;
                fbh[np * 2 + 1][0] = r2; fbh[np * 2 + 1][1] = r3;
                ldm_x4(r0, r1, r2, r3, base + OFF_BLg + sw128(ro));
                fbl[np * 2 + 0][0] = r0; fbl[np * 2 + 0][1] = r1;
                fbl[np * 2 + 1][0] = r2; fbl[np * 2 + 1][1] = r3;
            }
#pragma unroll
            for (int mf = 0; mf < 4; mf++)
#pragma unroll
                for (int nf = 0; nf < 4; nf++) {
                    mma16816(acc[mf][nf], fah[mf], fbh[nf]);
                    mma16816(acc[mf][nf], fah[mf], fbl[nf]);
                    mma16816(acc[mf][nf], fal[mf], fbh[nf]);
                }
        }
        __syncthreads();
    }

    const int qr = l >> 2, qc = (l & 3) * 2;
#pragma unroll
    for (int mf = 0; mf < 4; mf++) {
#pragma unroll
        for (int nf = 0; nf < 4; nf++) {
            const int colg = brow0 + n0 + nf * 8 + qc;
            const bool first = !DUAL || (colg < En);
            const int col = first ? colg : colg - En;
            const float* bp = first ? bias : bias2;
            const float b0 = bp ? bp[col] : 0.0f;
            const float b1 = bp ? bp[col + 1] : 0.0f;
#pragma unroll
            for (int half = 0; half < 2; half++) {
                const int row = arow0 + m0 + mf * 16 + qr + half * 8;
                float v0 = acc[mf][nf][half * 2 + 0] + b0;
                float v1 = acc[mf][nf][half * 2 + 1] + b1;
                if (ACT == 1) {
                    v0 = v0 > 0.0f ? v0 : 0.01f * v0;
                    v1 = v1 > 0.0f ? v1 : 0.01f * v1;
                }
                const size_t o = (size_t)row * (DUAL ? En : N) + col;
                float* Cp = first ? C : C2;
                if (ADD_C) {
                    float2 old = *(float2*)(Cp + o);
                    v0 += old.x; v1 += old.y;
                }
                *(float2*)(Cp + o) = make_float2(v0, v1);
                if (DUAL) {
                    const float a = first ? salpha : 1.0f;
                    bf16* Sp = first ? Sh : S2h;
                    const float s0 = v0 * a, s1 = v1 * a;
                    *(__nv_bfloat162*)(Sp + o) =
                        __nv_bfloat162(__float2bfloat16(s0), __float2bfloat16(s1));
                } else if (WSPLIT >= 1) {
                    const float s0 = v0 * salpha, s1 = v1 * salpha;
                    const bf16 h0 = __float2bfloat16(s0);
                    const bf16 h1 = __float2bfloat16(s1);
                    Sh[o]     = h0;
                    Sh[o + 1] = h1;
                    if (WSPLIT == 2) {
                        Sl[o]     = __float2bfloat16(s0 - __bfloat162float(h0));
                        Sl[o + 1] = __float2bfloat16(s1 - __bfloat162float(h1));
                    }
                }
            }
        }
    }
}

// ===================== 1-term HMMA attn GEMM + per-tile ub max ===============
#define ATN_STG  32768
#define ATN_BH   16384

__global__ __launch_bounds__(256)
void attn_hmma_kernel(const bf16* __restrict__ Ah, const bf16* __restrict__ Bh,
                      const float* __restrict__ nA, const float* __restrict__ nB,
                      bf16* __restrict__ S,
                      float* __restrict__ PMV, int* __restrict__ PMI)
{
    extern __shared__ char smem[];
    const uint32_t sb = smem_u32(smem);
    const int tid = threadIdx.x;
    const int w = tid >> 5, l = tid & 31;
    const int m0 = (w & 1) * 64;
    const int n0 = (w >> 1) * 32;
    const int arow0 = blockIdx.y * 128;
    const int brow0 = blockIdx.x * 128;

    const int g  = l >> 3, lr = l & 7;
    const int ar  = (g & 1) * 8 + lr;
    const int acb = (g >> 1) * 16;
    const int br  = (g >> 1) * 8 + lr;
    const int bcb = (g & 1) * 16;

    float acc[4][4][4];
#pragma unroll
    for (int i = 0; i < 4; i++)
#pragma unroll
        for (int j = 0; j < 4; j++)
#pragma unroll
            for (int q = 0; q < 4; q++) acc[i][j][q] = 0.0f;

    auto load_stage = [&](int kc, int s) {
        const uint32_t base = sb + s * ATN_STG;
        const int kof = kc * 64;
#pragma unroll
        for (int i = 0; i < 4; i++) {
            const int v = tid + i * 256;
            const int r = v >> 3;
            const int cb = (v & 7) * 16;
            const uint32_t sw = sw128((uint32_t)(r * 128 + cb));
            const size_t ga = (size_t)(arow0 + r) * En + kof + (v & 7) * 8;
            const size_t gb = (size_t)(brow0 + r) * En + kof + (v & 7) * 8;
            cp_async16(base + sw, Ah + ga);
            cp_async16(base + ATN_BH + sw, Bh + gb);
        }
        cp_commit();
    };

    load_stage(0, 0);
    const int NKC = En / 64;
    for (int kc = 0; kc < NKC; kc++) {
        if (kc + 1 < NKC) { load_stage(kc + 1, (kc + 1) & 1); cp_wait1(); }
        else              { cp_wait0(); }
        __syncthreads();

        const uint32_t base = sb + (kc & 1) * ATN_STG;
#pragma unroll
        for (int ks = 0; ks < 4; ks++) {
            const int kb = ks * 32;
            uint32_t fah[4][4];
#pragma unroll
            for (int mf = 0; mf < 4; mf++) {
                const uint32_t ro = (uint32_t)((m0 + mf * 16 + ar) * 128 + kb + acb);
                ldm_x4(fah[mf][0], fah[mf][1], fah[mf][2], fah[mf][3],
                       base + sw128(ro));
            }
            uint32_t fbh[4][2];
#pragma unroll
            for (int np = 0; np < 2; np++) {
                const uint32_t ro = (uint32_t)((n0 + np * 16 + br) * 128 + kb + bcb);
                uint32_t r0, r1, r2, r3;
                ldm_x4(r0, r1, r2, r3, base + ATN_BH + sw128(ro));
                fbh[np * 2 + 0][0] = r0; fbh[np * 2 + 0][1] = r1;
                fbh[np * 2 + 1][0] = r2; fbh[np * 2 + 1][1] = r3;
            }
#pragma unroll
            for (int mf = 0; mf < 4; mf++)
#pragma unroll
                for (int nf = 0; nf < 4; nf++)
                    mma16816(acc[mf][nf], fah[mf], fbh[nf]);
        }
        __syncthreads();
    }

    const int qr = l >> 2, qc = (l & 3) * 2;
#pragma unroll
    for (int mf = 0; mf < 4; mf++) {
        const int row = arow0 + m0 + mf * 16 + qr;
#pragma unroll
        for (int nf = 0; nf < 4; nf++) {
            const int col = brow0 + n0 + nf * 8 + qc;
            __nv_bfloat162 p0(__float2bfloat16(acc[mf][nf][0]),
                              __float2bfloat16(acc[mf][nf][1]));
            __nv_bfloat162 p1(__float2bfloat16(acc[mf][nf][2]),
                              __float2bfloat16(acc[mf][nf][3]));
            stcs32(S + (size_t)row * Mn + col, *(uint32_t*)&p0);
            stcs32(S + (size_t)(row + 8) * Mn + col, *(uint32_t*)&p1);
        }
    }

    float nblo[8], nbhi[8];
#pragma unroll
    for (int nf = 0; nf < 4; nf++) {
#pragma unroll
        for (int q = 0; q < 2; q++) {
            const int j = brow0 + n0 + nf * 8 + qc + q;
            nblo[nf * 2 + q] = nB[j * 2 + 0];
            nbhi[nf * 2 + q] = nB[j * 2 + 1];
        }
    }

    float* smx = (float*)smem;
    int*   smi = (int*)(smem + 2048);
#pragma unroll
    for (int mf = 0; mf < 4; mf++) {
#pragma unroll
        for (int half = 0; half < 2; half++) {
            const int rowg = arow0 + m0 + mf * 16 + qr + half * 8;
            const float nalo = nA[rowg * 2 + 0];
            const float nahi = nA[rowg * 2 + 1];
            const int rowl = m0 + mf * 16 + qr + half * 8;
            float bmx = -INFINITY; int bmi = 0x7fffffff;
#pragma unroll
            for (int nf = 0; nf < 4; nf++) {
#pragma unroll
                for (int q = 0; q < 2; q++) {
                    const float ub = acc[mf][nf][half * 2 + q]
                                   + errb(nalo, nahi, nblo[nf * 2 + q], nbhi[nf * 2 + q]);
                    const int col = n0 + nf * 8 + qc + q;
                    if (better(ub, col, bmx, bmi)) { bmx = ub; bmi = col; }
                }
            }
#pragma unroll
            for (int o = 1; o <= 2; o <<= 1) {
                const float ov = __shfl_xor_sync(0xffffffffu, bmx, o);
                const int   oi = __shfl_xor_sync(0xffffffffu, bmi, o);
                if (better(ov, oi, bmx, bmi)) { bmx = ov; bmi = oi; }
            }
            if ((l & 3) == 0) { smx[rowl * 4 + (w >> 1)] = bmx; smi[rowl * 4 + (w >> 1)] = bmi; }
        }
    }
    __syncthreads();
    if (tid < 128) {
        float bmx = smx[tid * 4]; int bmi = smi[tid * 4];
#pragma unroll
        for (int c = 1; c < 4; c++) {
            const float ov = smx[tid * 4 + c]; const int oi = smi[tid * 4 + c];
            if (better(ov, oi, bmx, bmi)) { bmx = ov; bmi = oi; }
        }
        const size_t o = (size_t)(arow0 + tid) * NTILE + blockIdx.x;
        PMV[o] = bmx;
        PMI[o] = brow0 + bmi;
    }
}

// ---- merged row norms --------------------------------------------------------
__global__ void rownorm2_kernel(const float* __restrict__ EH,
                                const float* __restrict__ ET, float scale,
                                float* __restrict__ nA, float* __restrict__ nB)
{
    const int half = blockIdx.x >= (Mn / 8);
    const int rb = half ? blockIdx.x - Mn / 8 : blockIdx.x;
    const int row = rb * 8 + (threadIdx.x >> 5);
    const int lane = threadIdx.x & 31;
    const float* X = half ? ET : EH;
    const float alpha = half ? 1.0f : scale;
    float* nrm = half ? nB : nA;

    const float4* x4 = (const float4*)(X + (size_t)row * En);
    float slo = 0.0f, shi = 0.0f;
    for (int k = lane; k < En / 4; k += 32) {
        const float4 v = x4[k];
        const float a[4] = { v.x * alpha, v.y * alpha, v.z * alpha, v.w * alpha };
#pragma unroll
        for (int q = 0; q < 4; q++) {
            const float h = __bfloat162float(__float2bfloat16(a[q]));
            const float d = a[q] - h;
            slo += d * d;
            shi += h * h;
        }
    }
#pragma unroll
    for (int o = 16; o > 0; o >>= 1) {
        slo += __shfl_xor_sync(0xffffffffu, slo, o);
        shi += __shfl_xor_sync(0xffffffffu, shi, o);
    }
    if (lane == 0) {
        nrm[row * 2 + 0] = sqrtf(slo);
        nrm[row * 2 + 1] = sqrtf(shi);
    }
}

// ===================== fused certified top-6 + combine (128 threads) =========
__global__ __launch_bounds__(128)
void topk_combine_kernel(const bf16* __restrict__ S,
                         const float* __restrict__ PMV, const int* __restrict__ PMI,
                         const float* __restrict__ EH, const float* __restrict__ ET,
                         const float* __restrict__ nA, const float* __restrict__ nB,
                         float scale,
                         bf16* __restrict__ Uh, bf16* __restrict__ Ul,
                         bf16* __restrict__ Vh, bf16* __restrict__ Vl)
{
    const int row = blockIdx.x;
    const int t = threadIdx.x;
    const int lane = t & 31, wp = t >> 5;

    __shared__ float sh_eh[En];
    __shared__ float sh_nb[TKn][En];
    __shared__ float s_tmv[NTILE];
    __shared__ int   s_tmi[NTILE];
    __shared__ int   seedcol[NSEED];
    __shared__ float seedval[NSEED];
    __shared__ float sh_L;
    __shared__ float swv[4]; __shared__ int swi[4]; __shared__ int swt[4];
    __shared__ int   sh_win;
    __shared__ float w6[TKn]; __shared__ int idx6[TKn];
    __shared__ float p[TKn]; __shared__ float q[TKn];
    __shared__ float wred[4][2 * TKn];

    for (int k = t; k < En / 4; k += 128)
        ((float4*)sh_eh)[k] = ((const float4*)(EH + (size_t)row * En))[k];
    if (t < NTILE) {
        s_tmv[t] = PMV[(size_t)row * NTILE + t];
        s_tmi[t] = PMI[(size_t)row * NTILE + t];
    }
    __syncthreads();

    if (wp == 0) {
        float v0 = s_tmv[lane], v1 = s_tmv[lane + 32];
        int   i0 = lane, i1 = lane + 32;
        for (int s = 0; s < NSEED; s++) {
            float cv; int ct;
            if (v0 >= v1) { cv = v0; ct = i0; } else { cv = v1; ct = i1; }
#pragma unroll
            for (int o = 16; o > 0; o >>= 1) {
                const float ov = __shfl_xor_sync(0xffffffffu, cv, o);
                const int   ot = __shfl_xor_sync(0xffffffffu, ct, o);
                if (ov > cv || (ov == cv && ot < ct)) { cv = ov; ct = ot; }
            }
            if (lane == 0) seedcol[s] = s_tmi[ct];
            if (i0 == ct) v0 = -INFINITY;
            if (i1 == ct) v1 = -INFINITY;
        }
    }
    __syncthreads();

    const float4* eh4 = (const float4*)sh_eh;
    for (int r = 0; r < NSEED / 4; r++) {
        const int s = wp + 4 * r;
        const int j = seedcol[s];
        const float4* et4 = (const float4*)(ET + (size_t)j * En);
        float acc = 0.0f;
#pragma unroll
        for (int k = lane; k < En / 4; k += 32) {
            const float4 a = eh4[k];
            const float4 b = et4[k];
            acc += a.x * b.x + a.y * b.y + a.z * b.z + a.w * b.w;
        }
#pragma unroll
        for (int o = 16; o > 0; o >>= 1) acc += __shfl_xor_sync(0xffffffffu, acc, o);
        if (lane == 0) seedval[s] = acc * scale;
    }
    __syncthreads();
    if (t == 0) {
        float top[TKn];
#pragma unroll
        for (int k = 0; k < TKn; k++) top[k] = -INFINITY;
        for (int s = 0; s < NSEED; s++) {
            float v = seedval[s];
            if (v > top[TKn - 1]) {
                top[TKn - 1] = v;
#pragma unroll
                for (int k = TKn - 1; k > 0; k--)
                    if (top[k] > top[k - 1]) { float tv = top[k]; top[k] = top[k - 1]; top[k - 1] = tv; }
            }
        }
        sh_L = top[TKn - 1];
    }
    __syncthreads();
    const float L = sh_L;

    const float nalo = nA[row * 2 + 0], nahi = nA[row * 2 + 1];
    float lv[TKn]; int li[TKn];
#pragma unroll
    for (int k = 0; k < TKn; k++) { lv[k] = -INFINITY; li[k] = 0x7fffffff; }

    for (int tile = 0; tile < NTILE; tile++) {
        if (s_tmv[tile] < L) continue;
        const int col = tile * 128 + t;
        const uint16_t raw = ldcs16(S + (size_t)row * Mn + col);
        const float ap = __bfloat162float(*(const bf16*)&raw);
        const float nbh = nB[col * 2 + 1];
        const float b = errb(nalo, nahi, nB[col * 2 + 0], nbh) + 0.005f * nahi * nbh;
        const bool pass = (ap + b >= L);
        unsigned mask = __ballot_sync(0xffffffffu, pass);
        while (mask) {
            const int src = __ffs(mask) - 1;
            mask &= mask - 1;
            const int j = __shfl_sync(0xffffffffu, col, src);
            const float4* et4 = (const float4*)(ET + (size_t)j * En);
            float acc = 0.0f;
#pragma unroll
            for (int k = lane; k < En / 4; k += 32) {
                const float4 a = eh4[k];
                const float4 bb = et4[k];
                acc += a.x * bb.x + a.y * bb.y + a.z * bb.z + a.w * bb.w;
            }
#pragma unroll
            for (int o = 16; o > 0; o >>= 1) acc += __shfl_xor_sync(0xffffffffu, acc, o);
            if (lane == src) {
                const float s = acc * scale;
                if (better(s, j, lv[TKn - 1], li[TKn - 1])) {
                    lv[TKn - 1] = s; li[TKn - 1] = j;
#pragma unroll
                    for (int k = TKn - 1; k > 0; k--) {
                        if (better(lv[k], li[k], lv[k - 1], li[k - 1])) {
                            float tv = lv[k]; lv[k] = lv[k - 1]; lv[k - 1] = tv;
                            int   ti = li[k]; li[k] = li[k - 1]; li[k - 1] = ti;
                        }
                    }
                }
            }
        }
    }

    __shared__ float sv[128 * TKn];
    __shared__ int   si[128 * TKn];
    __shared__ int   sp[128];
#pragma unroll
    for (int k = 0; k < TKn; k++) { sv[t * TKn + k] = lv[k]; si[t * TKn + k] = li[k]; }
    sp[t] = 0;
    __syncthreads();
    for (int sel = 0; sel < TKn; sel++) {
        const int pp = sp[t];
        float cv = sv[t * TKn + pp];
        int   ci = si[t * TKn + pp];
        int   tt = t;
#pragma unroll
        for (int o = 16; o > 0; o >>= 1) {
            const float ov = __shfl_xor_sync(0xffffffffu, cv, o);
            const int   oi = __shfl_xor_sync(0xffffffffu, ci, o);
            const int   ot = __shfl_xor_sync(0xffffffffu, tt, o);
            if (better(ov, oi, cv, ci)) { cv = ov; ci = oi; tt = ot; }
        }
        if (lane == 0) { swv[wp] = cv; swi[wp] = ci; swt[wp] = tt; }
        __syncthreads();
        if (t == 0) {
            int wi = 0;
#pragma unroll
            for (int c = 1; c < 4; c++)
                if (better(swv[c], swi[c], swv[wi], swi[wi])) wi = c;
            w6[sel] = swv[wi];
            idx6[sel] = swi[wi];
            sh_win = swt[wi];
        }
        __syncthreads();
        if (t == sh_win && sp[t] < TKn - 1) sp[t]++;
        __syncthreads();
    }

    // fused combine phase
#pragma unroll
    for (int k = 0; k < TKn; k++) {
        const float4* src = (const float4*)(ET + (size_t)idx6[k] * En);
        for (int e = t; e < En / 4; e += 128) ((float4*)sh_nb[k])[e] = src[e];
    }
    if (t == 0) {
        float mx = w6[0];
        for (int k = 1; k < TKn; k++) mx = fmaxf(mx, w6[k]);
        float s = 0.0f;
        for (int k = 0; k < TKn; k++) { p[k] = expf(w6[k] - mx); s += p[k]; }
        float inv = 1.0f / s;
        for (int k = 0; k < TKn; k++) p[k] *= inv;
    }
    __syncthreads();

    float pn[TKn], pg[TKn];
#pragma unroll
    for (int k = 0; k < TKn; k++) { pn[k] = 0.0f; pg[k] = 0.0f; }
    for (int e = t; e < En; e += 128) {
        const float eh = sh_eh[e];
#pragma unroll
        for (int k = 0; k < TKn; k++) {
            const float nb = sh_nb[k][e];
            pn[k] += nb;
            pg[k] += tanhf((2.0f - p[k]) * eh + p[k] * nb);
        }
    }
#pragma unroll
    for (int k = 0; k < TKn; k++) {
#pragma unroll
        for (int o = 16; o > 0; o >>= 1) {
            pn[k] += __shfl_xor_sync(0xffffffffu, pn[k], o);
            pg[k] += __shfl_xor_sync(0xffffffffu, pg[k], o);
        }
    }
    if (lane == 0) {
#pragma unroll
        for (int k = 0; k < TKn; k++) {
            wred[wp][k] = pn[k];
            wred[wp][TKn + k] = pg[k];
        }
    }
    __syncthreads();
    if (t == 0) {
        float ka[TKn];
        float mx = -INFINITY;
#pragma unroll
        for (int k = 0; k < TKn; k++) {
            float sn = 0.0f, sg = 0.0f;
#pragma unroll
            for (int c = 0; c < 4; c++) { sn += wred[c][k]; sg += wred[c][TKn + k]; }
            ka[k] = sn * sg;
            mx = fmaxf(mx, ka[k]);
        }
        float s = 0.0f;
        for (int k = 0; k < TKn; k++) { q[k] = expf(ka[k] - mx); s += q[k]; }
        float inv = 1.0f / s;
        for (int k = 0; k < TKn; k++) q[k] *= inv;
    }
    __syncthreads();

    for (int e = t; e < En; e += 128) {
        float en = 0.0f;
#pragma unroll
        for (int k = 0; k < TKn; k++) en = fmaf(q[k], sh_nb[k][e], en);
        const float eh = sh_eh[e];
        const size_t o = (size_t)row * En + e;
        const float u = eh + en, v = eh * en;
        const bf16 uh = __float2bfloat16(u);
        const bf16 vh = __float2bfloat16(v);
        Uh[o] = uh; Ul[o] = __float2bfloat16(u - __bfloat162float(uh));
        Vh[o] = vh; Vl[o] = __float2bfloat16(v - __bfloat162float(vh));
    }
}

// ---- column partial reduce (optionally row-weighted) -----------------------
template<bool W>
__global__ void colred_kernel(const float* __restrict__ X,
                              const float* __restrict__ wgt,
                              float* __restrict__ part, int rows, int cols)
{
    const int col   = blockIdx.x * blockDim.x + threadIdx.x;
    const int chunk = blockIdx.y;
    const int rpc   = rows / gridDim.y;
    const int r0    = chunk * rpc;
    float s = 0.0f;
    for (int r = r0; r < r0 + rpc; r++) {
        float v = X[(size_t)r * cols + col];
        if (W) v *= wgt[r];
        s += v;
    }
    part[chunk * cols + col] = s;
}

// ---- parallel chunk-sum -------------------------------------------------------
__global__ void chunksum_kernel(const float* __restrict__ part,
                                float* __restrict__ outv, float mul)
{
    const int col = blockIdx.x * 8 + (threadIdx.x >> 5);
    const int lane = threadIdx.x & 31;
    float s = 0.0f;
#pragma unroll
    for (int c = lane; c < 256; c += 32) s += part[c * En + col];
#pragma unroll
    for (int o = 16; o > 0; o >>= 1) s += __shfl_xor_sync(0xffffffffu, s, o);
    if (lane == 0) outv[col] = s * mul;
}

__global__ void meanscale_split_kernel(const float* __restrict__ H,
                                       const float* __restrict__ cm,
                                       bf16* __restrict__ hh, bf16* __restrict__ hl)
{
    const int i4 = (blockIdx.x * blockDim.x + threadIdx.x) * 4;
    const int e = i4 & (En - 1);
    const float4 hv = *(const float4*)(H + i4);
    const float4 cv = *(const float4*)(cm + e);
    float v[4] = { (hv.x + cv.x) * 0.5f, (hv.y + cv.y) * 0.5f,
                   (hv.z + cv.z) * 0.5f, (hv.w + cv.w) * 0.5f };
    bf16 hi[4], lo[4];
#pragma unroll
    for (int k = 0; k < 4; k++) {
        hi[k] = __float2bfloat16(v[k]);
        lo[k] = __float2bfloat16(v[k] - __bfloat162float(hi[k]));
    }
    *(__nv_bfloat162*)(hh + i4)     = __nv_bfloat162(hi[0], hi[1]);
    *(__nv_bfloat162*)(hh + i4 + 2) = __nv_bfloat162(hi[2], hi[3]);
    *(__nv_bfloat162*)(hl + i4)     = __nv_bfloat162(lo[0], lo[1]);
    *(__nv_bfloat162*)(hl + i4 + 2) = __nv_bfloat162(lo[2], lo[3]);
}

// ---- g = G1 @ a2_w^T + a2_b -------------------------------------------------
__global__ void matvec_kernel(const float* __restrict__ G1,
                              const float* __restrict__ a2w,
                              const float* __restrict__ a2b,
                              float* __restrict__ gv)
{
    const int warp = (blockIdx.x * blockDim.x + threadIdx.x) >> 5;
    const int lane = threadIdx.x & 31;
    if (warp >= Mn) return;
    const float* rowp = G1 + (size_t)warp * (En / 2);
    float s = 0.0f;
    for (int j = lane; j < En / 2; j += 32) s = fmaf(rowp[j], a2w[j], s);
#pragma unroll
    for (int o = 16; o > 0; o >>= 1) s += __shfl_xor_sync(0xffffffffu, s, o);
    if (lane == 0) gv[warp] = s + a2b[0];
}

__global__ void softmax_att_kernel(const float* __restrict__ gv, float* __restrict__ att)
{
    __shared__ float red[1024];
    const int tid = threadIdx.x;
    float mx = -INFINITY;
    for (int i = tid; i < Mn; i += 1024) mx = fmaxf(mx, gv[i]);
    red[tid] = mx; __syncthreads();
    for (int s = 512; s > 0; s >>= 1) { if (tid < s) red[tid] = fmaxf(red[tid], red[tid + s]); __syncthreads(); }
    mx = red[0]; __syncthreads();
    float se = 0.0f;
    for (int i = tid; i < Mn; i += 1024) se += expf(gv[i] - mx);
    red[tid] = se; __syncthreads();
    for (int s = 512; s > 0; s >>= 1) { if (tid < s) red[tid] += red[tid + s]; __syncthreads(); }
    const float inv = 1.0f / red[0];
    for (int i = tid; i < Mn; i += 1024) att[i] = expf(gv[i] - mx) * inv;
}

__global__ void ln_kernel(const float* __restrict__ pooled,
                          const float* __restrict__ g,
                          const float* __restrict__ b,
                          float* __restrict__ out)
{
    __shared__ float red[En];
    const int e = threadIdx.x;
    const float s = pooled[e];
    red[e] = s; __syncthreads();
    for (int st = 256; st > 0; st >>= 1) { if (e < st) red[e] += red[e + st]; __syncthreads(); }
    const float mu = red[0] * (1.0f / (float)En);
    __syncthreads();
    const float d = s - mu;
    red[e] = d * d; __syncthreads();
    for (int st = 256; st > 0; st >>= 1) { if (e < st) red[e] += red[e + st]; __syncthreads(); }
    const float var = red[0] * (1.0f / (float)En);
    out[e] = d * rsqrtf(var + 1e-5f) * g[e] + b[e];
}

// --------------------------------------------------------------------------
extern "C" void kernel_launch(void* const* d_in, const int* in_sizes, int n_in,
                              void* d_out, int out_size)
{
    (void)in_sizes; (void)n_in; (void)out_size;
    const float* x    = (const float*)d_in[0];
    const float* fc1w = (const float*)d_in[1];
    const float* fc1b = (const float*)d_in[2];
    const float* whw  = (const float*)d_in[3];
    const float* whb  = (const float*)d_in[4];
    const float* wtw  = (const float*)d_in[5];
    const float* wtb  = (const float*)d_in[6];
    const float* l1w  = (const float*)d_in[7];
    const float* l1b  = (const float*)d_in[8];
    const float* l2w  = (const float*)d_in[9];
    const float* l2b  = (const float*)d_in[10];
    const float* a1w  = (const float*)d_in[11];
    const float* a1b  = (const float*)d_in[12];
    const float* a2w  = (const float*)d_in[13];
    const float* a2b  = (const float*)d_in[14];
    const float* lng  = (const float*)d_in[15];
    const float* lnb  = (const float*)d_in[16];
    float* out = (float*)d_out;

    float *H, *EH, *ET, *PMV, *NA, *NB, *EMB, *G1, *GV, *ATT, *PART, *CM, *POOL;
    bf16 *S, *AH, *BH, *XH, *XL, *HH, *HL, *UH, *UL, *VH, *VL, *MH, *ML;
    bf16 *Wfc1H, *Wfc1L, *WhtH, *WhtL, *Wl1H, *Wl1L, *Wl2H, *Wl2L, *Wa1H, *Wa1L;
    int *PMI;
    cudaGetSymbolAddress((void**)&H,    g_H);
    cudaGetSymbolAddress((void**)&EH,   g_EH);
    cudaGetSymbolAddress((void**)&ET,   g_ET);
    cudaGetSymbolAddress((void**)&S,    g_S);
    cudaGetSymbolAddress((void**)&PMV,  g_PMV);
    cudaGetSymbolAddress((void**)&PMI,  g_PMI);
    cudaGetSymbolAddress((void**)&NA,   g_NA);
    cudaGetSymbolAddress((void**)&NB,   g_NB);
    cudaGetSymbolAddress((void**)&AH,   g_AH);
    cudaGetSymbolAddress((void**)&BH,   g_BH);
    cudaGetSymbolAddress((void**)&XH,   g_XH);
    cudaGetSymbolAddress((void**)&XL,   g_XL);
    cudaGetSymbolAddress((void**)&HH,   g_HH);
    cudaGetSymbolAddress((void**)&HL,   g_HL);
    cudaGetSymbolAddress((void**)&UH,   g_UH);
    cudaGetSymbolAddress((void**)&UL,   g_UL);
    cudaGetSymbolAddress((void**)&VH,   g_VH);
    cudaGetSymbolAddress((void**)&VL,   g_VL);
    cudaGetSymbolAddress((void**)&MH,   g_MH);
    cudaGetSymbolAddress((void**)&ML,   g_ML);
    cudaGetSymbolAddress((void**)&Wfc1H, g_Wfc1H);
    cudaGetSymbolAddress((void**)&Wfc1L, g_Wfc1L);
    cudaGetSymbolAddress((void**)&WhtH,  g_WhtH);
    cudaGetSymbolAddress((void**)&WhtL,  g_WhtL);
    cudaGetSymbolAddress((void**)&Wl1H,  g_Wl1H);
    cudaGetSymbolAddress((void**)&Wl1L,  g_Wl1L);
    cudaGetSymbolAddress((void**)&Wl2H,  g_Wl2H);
    cudaGetSymbolAddress((void**)&Wl2L,  g_Wl2L);
    cudaGetSymbolAddress((void**)&Wa1H,  g_Wa1H);
    cudaGetSymbolAddress((void**)&Wa1L,  g_Wa1L);
    cudaGetSymbolAddress((void**)&EMB,  g_EMB);
    cudaGetSymbolAddress((void**)&G1,   g_G1);
    cudaGetSymbolAddress((void**)&GV,   g_GV);
    cudaGetSymbolAddress((void**)&ATT,  g_ATT);
    cudaGetSymbolAddress((void**)&PART, g_PART);
    cudaGetSymbolAddress((void**)&CM,   g_CM);
    cudaGetSymbolAddress((void**)&POOL, g_POOL);

    const float scale = 1.0f / sqrtf((float)En);

    cudaFuncSetAttribute(hgemm_nt<1, false, 0, false>, cudaFuncAttributeMaxDynamicSharedMemorySize, 2 * STG_BYTES);
    cudaFuncSetAttribute(hgemm_nt<0, false, 0, true >, cudaFuncAttributeMaxDynamicSharedMemorySize, 2 * STG_BYTES);
    cudaFuncSetAttribute(hgemm_nt<1, true,  2, false>, cudaFuncAttributeMaxDynamicSharedMemorySize, 2 * STG_BYTES);
    cudaFuncSetAttribute(attn_hmma_kernel, cudaFuncAttributeMaxDynamicSharedMemorySize, 2 * ATN_STG);

    // 0) mega-split: x + all weights (one launch)
    SplitArgs sa;
    sa.seg[0] = { x,    XH,    XL,    Mn * INn / 4 };
    sa.seg[1] = { fc1w, Wfc1H, Wfc1L, En * INn / 4 };
    sa.seg[2] = { whw,  WhtH,  WhtL,  En * En / 4 };
    sa.seg[3] = { wtw,  WhtH + En * En, WhtL + En * En, En * En / 4 };
    sa.seg[4] = { l1w,  Wl1H,  Wl1L,  En * En / 4 };
    sa.seg[5] = { l2w,  Wl2H,  Wl2L,  En * En / 4 };
    sa.seg[6] = { a1w,  Wa1H,  Wa1L,  (En / 2) * En / 4 };
    int totq = 0;
    for (int s = 0; s < 7; s++) totq += sa.seg[s].n4;
    megasplit_kernel<<<(totq + 255) / 256, 256>>>(sa);

    // 1) h = lrelu(x @ fc1^T + b)
    hgemm_nt<1, false, 0, false><<<dim3(En / 128, Mn / 128), 256, 2 * STG_BYTES>>>(
        XH, XL, Wfc1H, Wfc1L, fc1b, H, nullptr, nullptr, nullptr, nullptr, nullptr, 0.0f, En, INn);
    // 2) h = (h + colmean(h)) * 0.5  -> split
    colred_kernel<false><<<dim3(En / 128, 256), 128>>>(H, nullptr, PART, Mn, En);
    chunksum_kernel<<<En / 8, 256>>>(PART, CM, 1.0f / (float)Mn);
    meanscale_split_kernel<<<(Mn * En) / 1024, 256>>>(H, CM, HH, HL);
    // 3) fused e_h + e_t
    hgemm_nt<0, false, 0, true><<<dim3(2 * En / 128, Mn / 128), 256, 2 * STG_BYTES>>>(
        HH, HL, WhtH, WhtL, whb, EH, AH, nullptr, wtb, ET, BH, scale, En, En);
    rownorm2_kernel<<<Mn / 4, 256>>>(EH, ET, scale, NA, NB);
    // 4) S_approx = Ah @ Bh^T (1-term, bf16 .cs) + per-tile row ub maxima
    attn_hmma_kernel<<<dim3(NTILE, NTILE), 256, 2 * ATN_STG>>>(AH, BH, NA, NB, S, PMV, PMI);
    // 5+6) fused certified top-6 + combine (128 threads — best configuration)
    topk_combine_kernel<<<Mn, 128>>>(S, PMV, PMI, EH, ET, NA, NB, scale, UH, UL, VH, VL);
    // 7) emb = lrelu(U@l1^T+b) + lrelu(V@l2^T+b)
    hgemm_nt<1, false, 0, false><<<dim3(En / 128, Mn / 128), 256, 2 * STG_BYTES>>>(
        UH, UL, Wl1H, Wl1L, l1b, EMB, nullptr, nullptr, nullptr, nullptr, nullptr, 0.0f, En, En);
    hgemm_nt<1, true, 2, false><<<dim3(En / 128, Mn / 128), 256, 2 * STG_BYTES>>>(
        VH, VL, Wl2H, Wl2L, l2b, EMB, MH, ML, nullptr, nullptr, nullptr, 1.0f, En, En);
    // 8) readout gate
    hgemm_nt<1, false, 0, false><<<dim3((En / 2) / 128, Mn / 128), 256, 2 * STG_BYTES>>>(
        MH, ML, Wa1H, Wa1L, a1b, G1, nullptr, nullptr, nullptr, nullptr, nullptr, 0.0f, En / 2, En);
    matvec_kernel<<<Mn / 8, 256>>>(G1, a2w, a2b, GV);
    // 9) softmax over nodes, weighted pool, layernorm
    softmax_att_kernel<<<1, 1024>>>(GV, ATT);
    colred_kernel<true><<<dim3(En / 128, 256), 128>>>(EMB, ATT, PART, Mn, En);
    chunksum_kernel<<<En / 8, 256>>>(PART, POOL, 1.0f);
    ln_kernel<<<1, En>>>(POOL, lng, lnb, out);
}